// round 7
// baseline (speedup 1.0000x reference)
#include <cuda_runtime.h>
#include <cuda_fp16.h>
#include <math.h>
#include <stdint.h>

// ---------------- problem constants ----------------
static constexpr int kIN  = 128;
static constexpr int kH   = 4;
static constexpr int kC   = 64;
static constexpr int kHC  = 256;
static constexpr int kOUT = 512;
static constexpr int MAXN  = 50000;
static constexpr int MAXET = 850000;

// ---------------- scratch ----------------
__device__ float g_bufA[(size_t)MAXN * kHC];
__device__ float g_bufB[(size_t)MAXN * kHC];
__device__ float g_bufC[(size_t)MAXN * kHC];
__device__ float g_attn[6 * (size_t)MAXN * kH];   // [layer][src/dst][N*H], zeroed once
__device__ int   g_rowptr[MAXN + 1];
__device__ int   g_deg[MAXN];
__device__ int   g_adj[MAXET];
__device__ int   g_bsum[256];

// ---------------- helpers ----------------
__device__ __forceinline__ uint32_t cvt_tf32(float f) {
    uint32_t u;
    asm("cvt.rna.tf32.f32 %0, %1;" : "=r"(u) : "f"(f));
    return u;
}

__device__ __forceinline__ void mma_tf32_16x8x8(float* c, const uint32_t* a, const uint32_t* b) {
    asm volatile(
        "mma.sync.aligned.m16n8k8.row.col.f32.tf32.tf32.f32 "
        "{%0,%1,%2,%3}, {%4,%5,%6,%7}, {%8,%9}, {%0,%1,%2,%3};"
        : "+f"(c[0]), "+f"(c[1]), "+f"(c[2]), "+f"(c[3])
        : "r"(a[0]), "r"(a[1]), "r"(a[2]), "r"(a[3]), "r"(b[0]), "r"(b[1]));
}

// ---------------- tf32 mma.sync GEMM with fused attn epilogue ----------------
template <int BN, int AH, bool HIN, bool HOUT>
__global__ __launch_bounds__(256)
void tgemm_kernel(const void* __restrict__ Ain, const float* __restrict__ W,
                  void* __restrict__ Cout, int M, int K, int Nc,
                  const float* __restrict__ bias, int do_relu,
                  const float* __restrict__ avs, const float* __restrict__ avd,
                  float* __restrict__ as_n, float* __restrict__ ad_n)
{
    static constexpr int SA = 36;
    static constexpr int SB = BN + 8;
    static constexpr int NT = BN / 32;
    static constexpr int NB = 32 * (BN / 4) / 256;

    __shared__ uint32_t sA[128 * SA];
    __shared__ uint32_t sB[32 * SB];

    const int tid = threadIdx.x;
    const int wid = tid >> 5;
    const int lid = tid & 31;
    const int g   = lid >> 2;
    const int tig = lid & 3;
    const int warp_m = wid & 1;
    const int warp_n = wid >> 1;

    const int rowBase = blockIdx.y * 128;
    const int colBase = blockIdx.x * BN;

    float acc[4][NT][4];
#pragma unroll
    for (int mt = 0; mt < 4; mt++)
#pragma unroll
        for (int nt = 0; nt < NT; nt++)
#pragma unroll
            for (int i = 0; i < 4; i++) acc[mt][nt][i] = 0.f;

    float4 aRegF[4];
    uint4  aRegH[2];
    float4 wReg[NB];

    auto loadA = [&](int k0) {
        if (HIN) {
            const __half* A = (const __half*)Ain;
#pragma unroll
            for (int i = 0; i < 2; i++) {
                int idx = tid + 256 * i;
                int m = idx >> 2, c8 = idx & 3;
                int gr = rowBase + m;
                aRegH[i] = (gr < M) ? *(const uint4*)(A + (size_t)gr * K + k0 + c8 * 8)
                                    : make_uint4(0u, 0u, 0u, 0u);
            }
        } else {
            const float* A = (const float*)Ain;
#pragma unroll
            for (int i = 0; i < 4; i++) {
                int idx = tid + 256 * i;
                int m = idx >> 3, c4 = idx & 7;
                int gr = rowBase + m;
                aRegF[i] = (gr < M) ? *(const float4*)(A + (size_t)gr * K + k0 + c4 * 4)
                                    : make_float4(0.f, 0.f, 0.f, 0.f);
            }
        }
    };
    auto loadW = [&](int k0) {
#pragma unroll
        for (int i = 0; i < NB; i++) {
            int idx = tid + 256 * i;
            int k = idx / (BN / 4), c4 = idx % (BN / 4);
            wReg[i] = *(const float4*)(W + (size_t)(k0 + k) * Nc + colBase + c4 * 4);
        }
    };
    auto stsTiles = [&]() {
        if (HIN) {
#pragma unroll
            for (int i = 0; i < 2; i++) {
                int idx = tid + 256 * i;
                int m = idx >> 2, c8 = idx & 3;
                const __half* hp = (const __half*)&aRegH[i];
                uint32_t t[8];
#pragma unroll
                for (int j = 0; j < 8; j++) t[j] = cvt_tf32(__half2float(hp[j]));
                *(uint4*)(sA + m * SA + c8 * 8)     = make_uint4(t[0], t[1], t[2], t[3]);
                *(uint4*)(sA + m * SA + c8 * 8 + 4) = make_uint4(t[4], t[5], t[6], t[7]);
            }
        } else {
#pragma unroll
            for (int i = 0; i < 4; i++) {
                int idx = tid + 256 * i;
                int m = idx >> 3, c4 = idx & 7;
                float4 v = aRegF[i];
                *(uint4*)(sA + m * SA + c4 * 4) =
                    make_uint4(cvt_tf32(v.x), cvt_tf32(v.y), cvt_tf32(v.z), cvt_tf32(v.w));
            }
        }
#pragma unroll
        for (int i = 0; i < NB; i++) {
            int idx = tid + 256 * i;
            int k = idx / (BN / 4), c4 = idx % (BN / 4);
            float4 v = wReg[i];
            *(uint4*)(sB + k * SB + c4 * 4) =
                make_uint4(cvt_tf32(v.x), cvt_tf32(v.y), cvt_tf32(v.z), cvt_tf32(v.w));
        }
    };

    const int nchunk = K / 32;
    loadA(0);
    loadW(0);

    for (int ch = 0; ch < nchunk; ch++) {
        stsTiles();
        __syncthreads();
        if (ch + 1 < nchunk) { loadA((ch + 1) * 32); loadW((ch + 1) * 32); }

#pragma unroll
        for (int kk = 0; kk < 4; kk++) {
            const int kb = kk * 8;
            uint32_t afr[4][4];
#pragma unroll
            for (int mt = 0; mt < 4; mt++) {
                int m = warp_m * 64 + mt * 16 + g;
                afr[mt][0] = sA[(m)     * SA + kb + tig];
                afr[mt][1] = sA[(m + 8) * SA + kb + tig];
                afr[mt][2] = sA[(m)     * SA + kb + tig + 4];
                afr[mt][3] = sA[(m + 8) * SA + kb + tig + 4];
            }
            uint32_t bfr[NT][2];
#pragma unroll
            for (int nt = 0; nt < NT; nt++) {
                int n = warp_n * (BN / 4) + nt * 8 + g;
                bfr[nt][0] = sB[(kb + tig)     * SB + n];
                bfr[nt][1] = sB[(kb + tig + 4) * SB + n];
            }
#pragma unroll
            for (int mt = 0; mt < 4; mt++)
#pragma unroll
                for (int nt = 0; nt < NT; nt++)
                    mma_tf32_16x8x8(acc[mt][nt], afr[mt], bfr[nt]);
        }
        __syncthreads();
    }

    // ---- fused attn partials ----
    if (AH > 0) {
        const int h = (AH == 1) ? 0 : ((colBase + warp_n * (BN / 4)) >> 6);
#pragma unroll
        for (int mt = 0; mt < 4; mt++) {
            float s0 = 0.f, s1 = 0.f, d0 = 0.f, d1 = 0.f;
#pragma unroll
            for (int nt = 0; nt < NT; nt++) {
                int col = colBase + warp_n * (BN / 4) + nt * 8 + tig * 2;
                float a0 = avs[col], a1 = avs[col + 1];
                float b0 = avd[col], b1 = avd[col + 1];
                s0 += acc[mt][nt][0] * a0 + acc[mt][nt][1] * a1;
                s1 += acc[mt][nt][2] * a0 + acc[mt][nt][3] * a1;
                d0 += acc[mt][nt][0] * b0 + acc[mt][nt][1] * b1;
                d1 += acc[mt][nt][2] * b0 + acc[mt][nt][3] * b1;
            }
#pragma unroll
            for (int off = 1; off <= 2; off <<= 1) {
                s0 += __shfl_xor_sync(0xFFFFFFFFu, s0, off);
                s1 += __shfl_xor_sync(0xFFFFFFFFu, s1, off);
                d0 += __shfl_xor_sync(0xFFFFFFFFu, d0, off);
                d1 += __shfl_xor_sync(0xFFFFFFFFu, d1, off);
            }
            if (tig == 0) {
                int row0 = rowBase + warp_m * 64 + mt * 16 + g;
                int row1 = row0 + 8;
                if (row0 < M) {
                    atomicAdd(&as_n[(size_t)row0 * AH + h], s0);
                    atomicAdd(&ad_n[(size_t)row0 * AH + h], d0);
                }
                if (row1 < M) {
                    atomicAdd(&as_n[(size_t)row1 * AH + h], s1);
                    atomicAdd(&ad_n[(size_t)row1 * AH + h], d1);
                }
            }
        }
    }

    // ---- store C ----
#pragma unroll
    for (int mt = 0; mt < 4; mt++) {
        int row0 = rowBase + warp_m * 64 + mt * 16 + g;
        int row1 = row0 + 8;
#pragma unroll
        for (int nt = 0; nt < NT; nt++) {
            int col = colBase + warp_n * (BN / 4) + nt * 8 + tig * 2;
            float bx = 0.f, by = 0.f;
            if (bias) { bx = bias[col]; by = bias[col + 1]; }
            float2 v0 = make_float2(acc[mt][nt][0] + bx, acc[mt][nt][1] + by);
            float2 v1 = make_float2(acc[mt][nt][2] + bx, acc[mt][nt][3] + by);
            if (do_relu) {
                v0.x = fmaxf(v0.x, 0.f); v0.y = fmaxf(v0.y, 0.f);
                v1.x = fmaxf(v1.x, 0.f); v1.y = fmaxf(v1.y, 0.f);
            }
            if (HOUT) {
                __half2* Ch = (__half2*)Cout;
                if (row0 < M) Ch[((size_t)row0 * Nc + col) >> 1] = __float22half2_rn(v0);
                if (row1 < M) Ch[((size_t)row1 * Nc + col) >> 1] = __float22half2_rn(v1);
            } else {
                float* Cf = (float*)Cout;
                if (row0 < M) *(float2*)(Cf + (size_t)row0 * Nc + col) = v0;
                if (row1 < M) *(float2*)(Cf + (size_t)row1 * Nc + col) = v1;
            }
        }
    }
}

// ---------------- CSR build ----------------
__global__ void count_kernel(const int* __restrict__ ei, int E, int N, int* __restrict__ deg)
{
    int e = blockIdx.x * blockDim.x + threadIdx.x;
    int ET = E + N;
    if (e >= ET) return;
    int d = (e < E) ? ei[E + e] : (e - E);
    atomicAdd(&deg[d], 1);
}

__global__ void scan1_kernel(const int* __restrict__ deg, int* __restrict__ rowptr,
                             int* __restrict__ bsum, int N)
{
    __shared__ int sh[1024];
    int i = blockIdx.x * 1024 + threadIdx.x;
    int v = (i < N) ? deg[i] : 0;
    sh[threadIdx.x] = v;
    __syncthreads();
#pragma unroll
    for (int off = 1; off < 1024; off <<= 1) {
        int t = (threadIdx.x >= off) ? sh[threadIdx.x - off] : 0;
        __syncthreads();
        sh[threadIdx.x] += t;
        __syncthreads();
    }
    if (i < N) rowptr[i + 1] = sh[threadIdx.x];
    if (threadIdx.x == 1023) bsum[blockIdx.x] = sh[1023];
}

__global__ void scan2_kernel(int* __restrict__ bsum, int nb)
{
    if (threadIdx.x == 0) {
        int acc = 0;
        for (int i = 0; i < nb; i++) { int t = bsum[i]; bsum[i] = acc; acc += t; }
    }
}

__global__ void scan3_kernel(int* __restrict__ rowptr, const int* __restrict__ bsum, int N)
{
    int i = blockIdx.x * 1024 + threadIdx.x;
    if (i < N) rowptr[i + 1] += bsum[blockIdx.x];
    if (i == 0) rowptr[0] = 0;
}

__global__ void fill_kernel(const int* __restrict__ ei, int E, int N,
                            const int* __restrict__ rowptr, int* __restrict__ cur,
                            int* __restrict__ adj)
{
    int e = blockIdx.x * blockDim.x + threadIdx.x;
    int ET = E + N;
    if (e >= ET) return;
    int s, d;
    if (e < E) { s = ei[e]; d = ei[E + e]; } else { s = d = e - E; }
    int pos = rowptr[d] + atomicAdd(&cur[d], 1);
    adj[pos] = s;
}

// ---------------- fused gather (adj-broadcast, half in/out) ----------------
__device__ __forceinline__ void acc8_half(float* acc, float a, uint4 r)
{
    const __half2* hp = (const __half2*)&r;
#pragma unroll
    for (int i = 0; i < 4; i++) {
        float2 f = __half22float2(hp[i]);
        acc[2 * i]     += a * f.x;
        acc[2 * i + 1] += a * f.y;
    }
}

__global__ __launch_bounds__(256) void gat_gather4_kernel(
    const int* __restrict__ rowptr, const int* __restrict__ adj,
    const __half* __restrict__ xl,
    const float* __restrict__ as_n, const float* __restrict__ ad_n,
    const float* __restrict__ bias, __half* __restrict__ out, int N)
{
    int w = (blockIdx.x * blockDim.x + threadIdx.x) >> 5;
    int lane = threadIdx.x & 31;
    if (w >= N) return;

    const int h   = lane >> 3;
    const int col = lane * 8;
    const float ad = ad_n[(size_t)w * 4 + h];

    float acc[8];
#pragma unroll
    for (int i = 0; i < 8; i++) acc[i] = 0.f;
    float den = 0.f;

    const int beg = rowptr[w], end = rowptr[w + 1];
    for (int j0 = beg; j0 < end; j0 += 32) {
        int myadj = (j0 + lane < end) ? adj[j0 + lane] : 0;
        int cnt = min(32, end - j0);
#pragma unroll 4
        for (int k = 0; k < cnt; k++) {
            int s = __shfl_sync(0xFFFFFFFFu, myadj, k);
            float l = as_n[(size_t)s * 4 + h] + ad;
            l = (l > 0.f) ? l : 0.2f * l;
            float a = __expf(l);
            uint4 r = *(const uint4*)(xl + (size_t)s * 256 + col);
            den += a;
            acc8_half(acc, a, r);
        }
    }

    float inv = 1.f / (den + 1e-16f);
    __half2 o[4];
#pragma unroll
    for (int i = 0; i < 4; i++) {
        float2 f;
        f.x = fmaxf(acc[2 * i]     * inv + bias[col + 2 * i],     0.f);
        f.y = fmaxf(acc[2 * i + 1] * inv + bias[col + 2 * i + 1], 0.f);
        o[i] = __float22half2_rn(f);
    }
    *(uint4*)(out + (size_t)w * 256 + col) = *(const uint4*)o;
}

__global__ __launch_bounds__(256) void gat_gather1_kernel(
    const int* __restrict__ rowptr, const int* __restrict__ adj,
    const __half* __restrict__ xl,
    const float* __restrict__ as_n, const float* __restrict__ ad_n,
    const float* __restrict__ bias, __half* __restrict__ out, int N)
{
    int w = (blockIdx.x * blockDim.x + threadIdx.x) >> 5;
    int lane = threadIdx.x & 31;
    if (w >= N) return;

    const int col = lane * 2;
    const float ad = ad_n[w];

    float acc0 = 0.f, acc1 = 0.f, den = 0.f;

    const int beg = rowptr[w], end = rowptr[w + 1];
    for (int j0 = beg; j0 < end; j0 += 32) {
        int myadj = (j0 + lane < end) ? adj[j0 + lane] : 0;
        int cnt = min(32, end - j0);
#pragma unroll 4
        for (int k = 0; k < cnt; k++) {
            int s = __shfl_sync(0xFFFFFFFFu, myadj, k);
            float l = as_n[s] + ad;
            l = (l > 0.f) ? l : 0.2f * l;
            float a = __expf(l);
            float2 f = __half22float2(*(const __half2*)(xl + (size_t)s * 64 + col));
            den += a;
            acc0 += a * f.x;
            acc1 += a * f.y;
        }
    }

    float inv = 1.f / (den + 1e-16f);
    float2 f;
    f.x = fmaxf(acc0 * inv + bias[col + 0], 0.f);
    f.y = fmaxf(acc1 * inv + bias[col + 1], 0.f);
    *(__half2*)(out + (size_t)w * 64 + col) = __float22half2_rn(f);
}

// ---------------- host orchestration ----------------
extern "C" void kernel_launch(void* const* d_in, const int* in_sizes, int n_in,
                              void* d_out, int out_size)
{
    const float* x   = (const float*)d_in[0];
    const int*   ei  = (const int*)d_in[1];
    const float* W1  = (const float*)d_in[2];
    const float* as1 = (const float*)d_in[3];
    const float* ad1 = (const float*)d_in[4];
    const float* b1  = (const float*)d_in[5];
    const float* W2  = (const float*)d_in[6];
    const float* as2 = (const float*)d_in[7];
    const float* ad2 = (const float*)d_in[8];
    const float* b2  = (const float*)d_in[9];
    const float* W3  = (const float*)d_in[10];
    const float* as3 = (const float*)d_in[11];
    const float* ad3 = (const float*)d_in[12];
    const float* b3  = (const float*)d_in[13];
    const float* Wfc = (const float*)d_in[14];
    const float* bfc = (const float*)d_in[15];
    float* out = (float*)d_out;

    int N  = in_sizes[0] / kIN;
    int E  = in_sizes[1] / 2;
    int ET = E + N;

    float *bufA, *bufB, *bufC, *attn;
    int *rowptr, *deg, *adj, *bsum;
    cudaGetSymbolAddress((void**)&bufA, g_bufA);
    cudaGetSymbolAddress((void**)&bufB, g_bufB);
    cudaGetSymbolAddress((void**)&bufC, g_bufC);
    cudaGetSymbolAddress((void**)&attn, g_attn);
    cudaGetSymbolAddress((void**)&rowptr, g_rowptr);
    cudaGetSymbolAddress((void**)&deg,    g_deg);
    cudaGetSymbolAddress((void**)&adj,    g_adj);
    cudaGetSymbolAddress((void**)&bsum,   g_bsum);

    // per-layer attention slices (one contiguous zeroed region)
    size_t NH = (size_t)N * kH;
    float* pas1 = attn;
    float* pad1 = attn + NH;
    float* pas2 = attn + 2 * NH;
    float* pad2 = attn + 3 * NH;
    float* pas3 = attn + 4 * NH;
    float* pad3 = attn + 5 * NH;

    __half* bufAh = (__half*)bufA;
    __half* bufBh = (__half*)bufB;
    __half* bufCh = (__half*)bufC;

    int edgeBlocks = (ET + 255) / 256;
    int nodeWarpBlocks = (N + 7) / 8;
    int scanBlocks = (N + 1023) / 1024;

    dim3 grid256((kHC + 127) / 128, (N + 127) / 128);
    dim3 grid64(1, (N + 127) / 128);
    dim3 gridFC(kOUT / 128, (N + 127) / 128);

    // ---- CSR build + single attn zeroing ----
    cudaMemsetAsync(deg, 0, (size_t)N * sizeof(int));
    cudaMemsetAsync(attn, 0, 6 * NH * sizeof(float));
    count_kernel<<<edgeBlocks, 256>>>(ei, E, N, deg);
    scan1_kernel<<<scanBlocks, 1024>>>(deg, rowptr, bsum, N);
    scan2_kernel<<<1, 32>>>(bsum, scanBlocks);
    scan3_kernel<<<scanBlocks, 1024>>>(rowptr, bsum, N);
    cudaMemsetAsync(deg, 0, (size_t)N * sizeof(int));
    fill_kernel<<<edgeBlocks, 256>>>(ei, E, N, rowptr, deg, adj);

    // ---- layer 1 ----
    tgemm_kernel<128, 4, false, true><<<grid256, 256>>>(
        x, W1, bufA, N, kIN, kHC, nullptr, 0, as1, ad1, pas1, pad1);
    gat_gather4_kernel<<<nodeWarpBlocks, 256>>>(rowptr, adj, bufAh, pas1, pad1, b1, bufBh, N);

    // ---- layer 2 ----
    tgemm_kernel<128, 4, true, true><<<grid256, 256>>>(
        bufBh, W2, bufA, N, kHC, kHC, nullptr, 0, as2, ad2, pas2, pad2);
    gat_gather4_kernel<<<nodeWarpBlocks, 256>>>(rowptr, adj, bufAh, pas2, pad2, b2, bufCh, N);

    // ---- layer 3 ----
    tgemm_kernel<64, 1, true, true><<<grid64, 256>>>(
        bufCh, W3, bufA, N, kHC, kC, nullptr, 0, as3, ad3, pas3, pad3);
    gat_gather1_kernel<<<nodeWarpBlocks, 256>>>(rowptr, adj, bufAh, pas3, pad3, b3, bufBh, N);

    // ---- final fc ----
    tgemm_kernel<128, 0, true, false><<<gridFC, 256>>>(
        bufBh, Wfc, out, N, kC, kOUT, bfc, 1, nullptr, nullptr, nullptr, nullptr);
}

// round 8
// speedup vs baseline: 1.0609x; 1.0609x over previous
#include <cuda_runtime.h>
#include <cuda_fp16.h>
#include <math.h>
#include <stdint.h>

// ---------------- problem constants ----------------
static constexpr int kIN  = 128;
static constexpr int kH   = 4;
static constexpr int kC   = 64;
static constexpr int kHC  = 256;
static constexpr int kOUT = 512;
static constexpr int MAXN  = 50000;
static constexpr int MAXET = 850000;

// ---------------- scratch ----------------
__device__ float g_bufA[(size_t)MAXN * kHC];
__device__ float g_bufB[(size_t)MAXN * kHC];
__device__ float g_bufC[(size_t)MAXN * kHC];
__device__ float g_attn[6 * (size_t)MAXN * kH];
__device__ int   g_rowptr[MAXN + 1];
__device__ int   g_deg[MAXN];
__device__ int   g_adj[MAXET];
__device__ int   g_bsum[256];

// ---------------- helpers ----------------
__device__ __forceinline__ uint32_t cvt_tf32(float f) {
    uint32_t u;
    asm("cvt.rna.tf32.f32 %0, %1;" : "=r"(u) : "f"(f));
    return u;
}

__device__ __forceinline__ void mma_tf32_16x8x8(float* c, const uint32_t* a, const uint32_t* b) {
    asm volatile(
        "mma.sync.aligned.m16n8k8.row.col.f32.tf32.tf32.f32 "
        "{%0,%1,%2,%3}, {%4,%5,%6,%7}, {%8,%9}, {%0,%1,%2,%3};"
        : "+f"(c[0]), "+f"(c[1]), "+f"(c[2]), "+f"(c[3])
        : "r"(a[0]), "r"(a[1]), "r"(a[2]), "r"(a[3]), "r"(b[0]), "r"(b[1]));
}

// ---------------- tf32 mma.sync GEMM with fused attn epilogue ----------------
template <int BN, int AH, bool HIN, bool HOUT>
__global__ __launch_bounds__(256)
void tgemm_kernel(const void* __restrict__ Ain, const float* __restrict__ W,
                  void* __restrict__ Cout, int M, int K, int Nc,
                  const float* __restrict__ bias, int do_relu,
                  const float* __restrict__ avs, const float* __restrict__ avd,
                  float* __restrict__ as_n, float* __restrict__ ad_n)
{
    static constexpr int SA = 36;
    static constexpr int SB = BN + 8;
    static constexpr int NT = BN / 32;
    static constexpr int NB = 32 * (BN / 4) / 256;

    __shared__ uint32_t sA[128 * SA];
    __shared__ uint32_t sB[32 * SB];

    const int tid = threadIdx.x;
    const int wid = tid >> 5;
    const int lid = tid & 31;
    const int g   = lid >> 2;
    const int tig = lid & 3;
    const int warp_m = wid & 1;
    const int warp_n = wid >> 1;

    const int rowBase = blockIdx.y * 128;
    const int colBase = blockIdx.x * BN;

    float acc[4][NT][4];
#pragma unroll
    for (int mt = 0; mt < 4; mt++)
#pragma unroll
        for (int nt = 0; nt < NT; nt++)
#pragma unroll
            for (int i = 0; i < 4; i++) acc[mt][nt][i] = 0.f;

    float4 aRegF[4];
    uint4  aRegH[2];
    float4 wReg[NB];

    auto loadA = [&](int k0) {
        if (HIN) {
            const __half* A = (const __half*)Ain;
#pragma unroll
            for (int i = 0; i < 2; i++) {
                int idx = tid + 256 * i;
                int m = idx >> 2, c8 = idx & 3;
                int gr = rowBase + m;
                aRegH[i] = (gr < M) ? *(const uint4*)(A + (size_t)gr * K + k0 + c8 * 8)
                                    : make_uint4(0u, 0u, 0u, 0u);
            }
        } else {
            const float* A = (const float*)Ain;
#pragma unroll
            for (int i = 0; i < 4; i++) {
                int idx = tid + 256 * i;
                int m = idx >> 3, c4 = idx & 7;
                int gr = rowBase + m;
                aRegF[i] = (gr < M) ? *(const float4*)(A + (size_t)gr * K + k0 + c4 * 4)
                                    : make_float4(0.f, 0.f, 0.f, 0.f);
            }
        }
    };
    auto loadW = [&](int k0) {
#pragma unroll
        for (int i = 0; i < NB; i++) {
            int idx = tid + 256 * i;
            int k = idx / (BN / 4), c4 = idx % (BN / 4);
            wReg[i] = *(const float4*)(W + (size_t)(k0 + k) * Nc + colBase + c4 * 4);
        }
    };
    auto stsTiles = [&]() {
        if (HIN) {
#pragma unroll
            for (int i = 0; i < 2; i++) {
                int idx = tid + 256 * i;
                int m = idx >> 2, c8 = idx & 3;
                const __half* hp = (const __half*)&aRegH[i];
                uint32_t t[8];
#pragma unroll
                for (int j = 0; j < 8; j++) t[j] = cvt_tf32(__half2float(hp[j]));
                *(uint4*)(sA + m * SA + c8 * 8)     = make_uint4(t[0], t[1], t[2], t[3]);
                *(uint4*)(sA + m * SA + c8 * 8 + 4) = make_uint4(t[4], t[5], t[6], t[7]);
            }
        } else {
#pragma unroll
            for (int i = 0; i < 4; i++) {
                int idx = tid + 256 * i;
                int m = idx >> 3, c4 = idx & 7;
                float4 v = aRegF[i];
                *(uint4*)(sA + m * SA + c4 * 4) =
                    make_uint4(cvt_tf32(v.x), cvt_tf32(v.y), cvt_tf32(v.z), cvt_tf32(v.w));
            }
        }
#pragma unroll
        for (int i = 0; i < NB; i++) {
            int idx = tid + 256 * i;
            int k = idx / (BN / 4), c4 = idx % (BN / 4);
            float4 v = wReg[i];
            *(uint4*)(sB + k * SB + c4 * 4) =
                make_uint4(cvt_tf32(v.x), cvt_tf32(v.y), cvt_tf32(v.z), cvt_tf32(v.w));
        }
    };

    const int nchunk = K / 32;
    loadA(0);
    loadW(0);

    for (int ch = 0; ch < nchunk; ch++) {
        stsTiles();
        __syncthreads();
        if (ch + 1 < nchunk) { loadA((ch + 1) * 32); loadW((ch + 1) * 32); }

#pragma unroll
        for (int kk = 0; kk < 4; kk++) {
            const int kb = kk * 8;
            uint32_t afr[4][4];
#pragma unroll
            for (int mt = 0; mt < 4; mt++) {
                int m = warp_m * 64 + mt * 16 + g;
                afr[mt][0] = sA[(m)     * SA + kb + tig];
                afr[mt][1] = sA[(m + 8) * SA + kb + tig];
                afr[mt][2] = sA[(m)     * SA + kb + tig + 4];
                afr[mt][3] = sA[(m + 8) * SA + kb + tig + 4];
            }
            uint32_t bfr[NT][2];
#pragma unroll
            for (int nt = 0; nt < NT; nt++) {
                int n = warp_n * (BN / 4) + nt * 8 + g;
                bfr[nt][0] = sB[(kb + tig)     * SB + n];
                bfr[nt][1] = sB[(kb + tig + 4) * SB + n];
            }
#pragma unroll
            for (int mt = 0; mt < 4; mt++)
#pragma unroll
                for (int nt = 0; nt < NT; nt++)
                    mma_tf32_16x8x8(acc[mt][nt], afr[mt], bfr[nt]);
        }
        __syncthreads();
    }

    // ---- fused attn partials ----
    if (AH > 0) {
        const int h = (AH == 1) ? 0 : ((colBase + warp_n * (BN / 4)) >> 6);
#pragma unroll
        for (int mt = 0; mt < 4; mt++) {
            float s0 = 0.f, s1 = 0.f, d0 = 0.f, d1 = 0.f;
#pragma unroll
            for (int nt = 0; nt < NT; nt++) {
                int col = colBase + warp_n * (BN / 4) + nt * 8 + tig * 2;
                float a0 = avs[col], a1 = avs[col + 1];
                float b0 = avd[col], b1 = avd[col + 1];
                s0 += acc[mt][nt][0] * a0 + acc[mt][nt][1] * a1;
                s1 += acc[mt][nt][2] * a0 + acc[mt][nt][3] * a1;
                d0 += acc[mt][nt][0] * b0 + acc[mt][nt][1] * b1;
                d1 += acc[mt][nt][2] * b0 + acc[mt][nt][3] * b1;
            }
#pragma unroll
            for (int off = 1; off <= 2; off <<= 1) {
                s0 += __shfl_xor_sync(0xFFFFFFFFu, s0, off);
                s1 += __shfl_xor_sync(0xFFFFFFFFu, s1, off);
                d0 += __shfl_xor_sync(0xFFFFFFFFu, d0, off);
                d1 += __shfl_xor_sync(0xFFFFFFFFu, d1, off);
            }
            if (tig == 0) {
                int row0 = rowBase + warp_m * 64 + mt * 16 + g;
                int row1 = row0 + 8;
                if (row0 < M) {
                    atomicAdd(&as_n[(size_t)row0 * AH + h], s0);
                    atomicAdd(&ad_n[(size_t)row0 * AH + h], d0);
                }
                if (row1 < M) {
                    atomicAdd(&as_n[(size_t)row1 * AH + h], s1);
                    atomicAdd(&ad_n[(size_t)row1 * AH + h], d1);
                }
            }
        }
    }

    // ---- store C ----
#pragma unroll
    for (int mt = 0; mt < 4; mt++) {
        int row0 = rowBase + warp_m * 64 + mt * 16 + g;
        int row1 = row0 + 8;
#pragma unroll
        for (int nt = 0; nt < NT; nt++) {
            int col = colBase + warp_n * (BN / 4) + nt * 8 + tig * 2;
            float bx = 0.f, by = 0.f;
            if (bias) { bx = bias[col]; by = bias[col + 1]; }
            float2 v0 = make_float2(acc[mt][nt][0] + bx, acc[mt][nt][1] + by);
            float2 v1 = make_float2(acc[mt][nt][2] + bx, acc[mt][nt][3] + by);
            if (do_relu) {
                v0.x = fmaxf(v0.x, 0.f); v0.y = fmaxf(v0.y, 0.f);
                v1.x = fmaxf(v1.x, 0.f); v1.y = fmaxf(v1.y, 0.f);
            }
            if (HOUT) {
                __half2* Ch = (__half2*)Cout;
                if (row0 < M) Ch[((size_t)row0 * Nc + col) >> 1] = __float22half2_rn(v0);
                if (row1 < M) Ch[((size_t)row1 * Nc + col) >> 1] = __float22half2_rn(v1);
            } else {
                float* Cf = (float*)Cout;
                if (row0 < M) *(float2*)(Cf + (size_t)row0 * Nc + col) = v0;
                if (row1 < M) *(float2*)(Cf + (size_t)row1 * Nc + col) = v1;
            }
        }
    }
}

// ---------------- CSR build ----------------
__global__ void count_kernel(const int* __restrict__ ei, int E, int N, int* __restrict__ deg)
{
    int e = blockIdx.x * blockDim.x + threadIdx.x;
    int ET = E + N;
    if (e >= ET) return;
    int d = (e < E) ? ei[E + e] : (e - E);
    atomicAdd(&deg[d], 1);
}

__global__ void scan1_kernel(const int* __restrict__ deg, int* __restrict__ rowptr,
                             int* __restrict__ bsum, int N)
{
    __shared__ int sh[1024];
    int i = blockIdx.x * 1024 + threadIdx.x;
    int v = (i < N) ? deg[i] : 0;
    sh[threadIdx.x] = v;
    __syncthreads();
#pragma unroll
    for (int off = 1; off < 1024; off <<= 1) {
        int t = (threadIdx.x >= off) ? sh[threadIdx.x - off] : 0;
        __syncthreads();
        sh[threadIdx.x] += t;
        __syncthreads();
    }
    if (i < N) rowptr[i + 1] = sh[threadIdx.x];
    if (threadIdx.x == 1023) bsum[blockIdx.x] = sh[1023];
}

__global__ void scan2_kernel(int* __restrict__ bsum, int nb)
{
    if (threadIdx.x == 0) {
        int acc = 0;
        for (int i = 0; i < nb; i++) { int t = bsum[i]; bsum[i] = acc; acc += t; }
    }
}

__global__ void scan3_kernel(int* __restrict__ rowptr, const int* __restrict__ bsum, int N)
{
    int i = blockIdx.x * 1024 + threadIdx.x;
    if (i < N) rowptr[i + 1] += bsum[blockIdx.x];
    if (i == 0) rowptr[0] = 0;
}

__global__ void fill_kernel(const int* __restrict__ ei, int E, int N,
                            const int* __restrict__ rowptr, int* __restrict__ cur,
                            int* __restrict__ adj)
{
    int e = blockIdx.x * blockDim.x + threadIdx.x;
    int ET = E + N;
    if (e >= ET) return;
    int s, d;
    if (e < E) { s = ei[e]; d = ei[E + e]; } else { s = d = e - E; }
    int pos = rowptr[d] + atomicAdd(&cur[d], 1);
    adj[pos] = s;
}

// ---------------- fused gather (4-way unroll, half in/out) ----------------
__device__ __forceinline__ void acc8_half(float* acc, float a, uint4 r)
{
    const __half2* hp = (const __half2*)&r;
#pragma unroll
    for (int i = 0; i < 4; i++) {
        float2 f = __half22float2(hp[i]);
        acc[2 * i]     += a * f.x;
        acc[2 * i + 1] += a * f.y;
    }
}

__device__ __forceinline__ float edge_alpha(float as_v, float ad)
{
    float l = as_v + ad;
    l = (l > 0.f) ? l : 0.2f * l;
    return __expf(l);
}

__global__ __launch_bounds__(256) void gat_gather4_kernel(
    const int* __restrict__ rowptr, const int* __restrict__ adj,
    const __half* __restrict__ xl,
    const float* __restrict__ as_n, const float* __restrict__ ad_n,
    const float* __restrict__ bias, __half* __restrict__ out, int N)
{
    int w = (blockIdx.x * blockDim.x + threadIdx.x) >> 5;
    int lane = threadIdx.x & 31;
    if (w >= N) return;

    const int h   = lane >> 3;
    const int col = lane * 8;
    const float ad = ad_n[(size_t)w * 4 + h];

    float acc[8];
#pragma unroll
    for (int i = 0; i < 8; i++) acc[i] = 0.f;
    float den = 0.f;

    const int beg = rowptr[w], end = rowptr[w + 1];
    int j = beg;
    for (; j + 3 < end; j += 4) {
        int s0 = adj[j], s1 = adj[j + 1], s2 = adj[j + 2], s3 = adj[j + 3];
        float a0 = edge_alpha(as_n[(size_t)s0 * 4 + h], ad);
        float a1 = edge_alpha(as_n[(size_t)s1 * 4 + h], ad);
        float a2 = edge_alpha(as_n[(size_t)s2 * 4 + h], ad);
        float a3 = edge_alpha(as_n[(size_t)s3 * 4 + h], ad);
        uint4 r0 = *(const uint4*)(xl + (size_t)s0 * 256 + col);
        uint4 r1 = *(const uint4*)(xl + (size_t)s1 * 256 + col);
        uint4 r2 = *(const uint4*)(xl + (size_t)s2 * 256 + col);
        uint4 r3 = *(const uint4*)(xl + (size_t)s3 * 256 + col);
        den += (a0 + a1) + (a2 + a3);
        acc8_half(acc, a0, r0);
        acc8_half(acc, a1, r1);
        acc8_half(acc, a2, r2);
        acc8_half(acc, a3, r3);
    }
    for (; j < end; j++) {
        int s = adj[j];
        float a = edge_alpha(as_n[(size_t)s * 4 + h], ad);
        uint4 r = *(const uint4*)(xl + (size_t)s * 256 + col);
        den += a;
        acc8_half(acc, a, r);
    }

    float inv = 1.f / (den + 1e-16f);
    __half2 o[4];
#pragma unroll
    for (int i = 0; i < 4; i++) {
        float2 f;
        f.x = fmaxf(acc[2 * i]     * inv + bias[col + 2 * i],     0.f);
        f.y = fmaxf(acc[2 * i + 1] * inv + bias[col + 2 * i + 1], 0.f);
        o[i] = __float22half2_rn(f);
    }
    *(uint4*)(out + (size_t)w * 256 + col) = *(const uint4*)o;
}

__global__ __launch_bounds__(256) void gat_gather1_kernel(
    const int* __restrict__ rowptr, const int* __restrict__ adj,
    const __half* __restrict__ xl,
    const float* __restrict__ as_n, const float* __restrict__ ad_n,
    const float* __restrict__ bias, __half* __restrict__ out, int N)
{
    int w = (blockIdx.x * blockDim.x + threadIdx.x) >> 5;
    int lane = threadIdx.x & 31;
    if (w >= N) return;

    const int col = lane * 2;
    const float ad = ad_n[w];

    float acc0 = 0.f, acc1 = 0.f, den = 0.f;

    const int beg = rowptr[w], end = rowptr[w + 1];
    int j = beg;
    for (; j + 3 < end; j += 4) {
        int s0 = adj[j], s1 = adj[j + 1], s2 = adj[j + 2], s3 = adj[j + 3];
        float a0 = edge_alpha(as_n[s0], ad);
        float a1 = edge_alpha(as_n[s1], ad);
        float a2 = edge_alpha(as_n[s2], ad);
        float a3 = edge_alpha(as_n[s3], ad);
        float2 f0 = __half22float2(*(const __half2*)(xl + (size_t)s0 * 64 + col));
        float2 f1 = __half22float2(*(const __half2*)(xl + (size_t)s1 * 64 + col));
        float2 f2 = __half22float2(*(const __half2*)(xl + (size_t)s2 * 64 + col));
        float2 f3 = __half22float2(*(const __half2*)(xl + (size_t)s3 * 64 + col));
        den += (a0 + a1) + (a2 + a3);
        acc0 += a0 * f0.x + a1 * f1.x + a2 * f2.x + a3 * f3.x;
        acc1 += a0 * f0.y + a1 * f1.y + a2 * f2.y + a3 * f3.y;
    }
    for (; j < end; j++) {
        int s = adj[j];
        float a = edge_alpha(as_n[s], ad);
        float2 f = __half22float2(*(const __half2*)(xl + (size_t)s * 64 + col));
        den += a;
        acc0 += a * f.x;
        acc1 += a * f.y;
    }

    float inv = 1.f / (den + 1e-16f);
    float2 f;
    f.x = fmaxf(acc0 * inv + bias[col + 0], 0.f);
    f.y = fmaxf(acc1 * inv + bias[col + 1], 0.f);
    *(__half2*)(out + (size_t)w * 64 + col) = __float22half2_rn(f);
}

// ---------------- host orchestration ----------------
extern "C" void kernel_launch(void* const* d_in, const int* in_sizes, int n_in,
                              void* d_out, int out_size)
{
    const float* x   = (const float*)d_in[0];
    const int*   ei  = (const int*)d_in[1];
    const float* W1  = (const float*)d_in[2];
    const float* as1 = (const float*)d_in[3];
    const float* ad1 = (const float*)d_in[4];
    const float* b1  = (const float*)d_in[5];
    const float* W2  = (const float*)d_in[6];
    const float* as2 = (const float*)d_in[7];
    const float* ad2 = (const float*)d_in[8];
    const float* b2  = (const float*)d_in[9];
    const float* W3  = (const float*)d_in[10];
    const float* as3 = (const float*)d_in[11];
    const float* ad3 = (const float*)d_in[12];
    const float* b3  = (const float*)d_in[13];
    const float* Wfc = (const float*)d_in[14];
    const float* bfc = (const float*)d_in[15];
    float* out = (float*)d_out;

    int N  = in_sizes[0] / kIN;
    int E  = in_sizes[1] / 2;
    int ET = E + N;

    float *bufA, *bufB, *bufC, *attn;
    int *rowptr, *deg, *adj, *bsum;
    cudaGetSymbolAddress((void**)&bufA, g_bufA);
    cudaGetSymbolAddress((void**)&bufB, g_bufB);
    cudaGetSymbolAddress((void**)&bufC, g_bufC);
    cudaGetSymbolAddress((void**)&attn, g_attn);
    cudaGetSymbolAddress((void**)&rowptr, g_rowptr);
    cudaGetSymbolAddress((void**)&deg,    g_deg);
    cudaGetSymbolAddress((void**)&adj,    g_adj);
    cudaGetSymbolAddress((void**)&bsum,   g_bsum);

    size_t NH = (size_t)N * kH;
    float* pas1 = attn;
    float* pad1 = attn + NH;
    float* pas2 = attn + 2 * NH;
    float* pad2 = attn + 3 * NH;
    float* pas3 = attn + 4 * NH;
    float* pad3 = attn + 5 * NH;

    __half* bufAh = (__half*)bufA;
    __half* bufBh = (__half*)bufB;
    __half* bufCh = (__half*)bufC;

    int edgeBlocks = (ET + 255) / 256;
    int nodeWarpBlocks = (N + 7) / 8;
    int scanBlocks = (N + 1023) / 1024;

    dim3 grid256((kHC + 127) / 128, (N + 127) / 128);
    dim3 grid64(1, (N + 127) / 128);
    dim3 gridFC(kOUT / 128, (N + 127) / 128);

    // side stream + events for CSR || GEMM1 overlap (created once; no device memory)
    static cudaStream_t s2 = nullptr;
    static cudaEvent_t evFork = nullptr, evJoin = nullptr;
    if (!s2) {
        cudaStreamCreateWithFlags(&s2, cudaStreamNonBlocking);
        cudaEventCreateWithFlags(&evFork, cudaEventDisableTiming);
        cudaEventCreateWithFlags(&evJoin, cudaEventDisableTiming);
    }

    // attn zeroing must precede layer-1 GEMM epilogue atomics (main stream)
    cudaMemsetAsync(attn, 0, 6 * NH * sizeof(float));

    // fork: CSR build on s2, concurrent with layer-1 GEMM on main stream
    cudaEventRecord(evFork, 0);
    cudaStreamWaitEvent(s2, evFork, 0);

    cudaMemsetAsync(deg, 0, (size_t)N * sizeof(int), s2);
    count_kernel<<<edgeBlocks, 256, 0, s2>>>(ei, E, N, deg);
    scan1_kernel<<<scanBlocks, 1024, 0, s2>>>(deg, rowptr, bsum, N);
    scan2_kernel<<<1, 32, 0, s2>>>(bsum, scanBlocks);
    scan3_kernel<<<scanBlocks, 1024, 0, s2>>>(rowptr, bsum, N);
    cudaMemsetAsync(deg, 0, (size_t)N * sizeof(int), s2);
    fill_kernel<<<edgeBlocks, 256, 0, s2>>>(ei, E, N, rowptr, deg, adj);
    cudaEventRecord(evJoin, s2);

    // ---- layer 1 GEMM (independent of CSR) ----
    tgemm_kernel<128, 4, false, true><<<grid256, 256>>>(
        x, W1, bufA, N, kIN, kHC, nullptr, 0, as1, ad1, pas1, pad1);

    // join before first gather (needs CSR)
    cudaStreamWaitEvent(0, evJoin, 0);

    gat_gather4_kernel<<<nodeWarpBlocks, 256>>>(rowptr, adj, bufAh, pas1, pad1, b1, bufBh, N);

    // ---- layer 2 ----
    tgemm_kernel<128, 4, true, true><<<grid256, 256>>>(
        bufBh, W2, bufA, N, kHC, kHC, nullptr, 0, as2, ad2, pas2, pad2);
    gat_gather4_kernel<<<nodeWarpBlocks, 256>>>(rowptr, adj, bufAh, pas2, pad2, b2, bufCh, N);

    // ---- layer 3 ----
    tgemm_kernel<64, 1, true, true><<<grid64, 256>>>(
        bufCh, W3, bufA, N, kHC, kC, nullptr, 0, as3, ad3, pas3, pad3);
    gat_gather1_kernel<<<nodeWarpBlocks, 256>>>(rowptr, adj, bufAh, pas3, pad3, b3, bufBh, N);

    // ---- final fc ----
    tgemm_kernel<128, 0, true, false><<<gridFC, 256>>>(
        bufBh, Wfc, out, N, kC, kOUT, bfc, 1, nullptr, nullptr, nullptr, nullptr);
}

// round 9
// speedup vs baseline: 1.1400x; 1.0745x over previous
#include <cuda_runtime.h>
#include <cuda_fp16.h>
#include <math.h>
#include <stdint.h>

// ---------------- problem constants ----------------
static constexpr int kIN  = 128;
static constexpr int kH   = 4;
static constexpr int kC   = 64;
static constexpr int kHC  = 256;
static constexpr int kOUT = 512;
static constexpr int MAXN  = 50000;
static constexpr int MAXET = 850000;

// ---------------- scratch ----------------
__device__ float g_bufA[(size_t)MAXN * kHC];
__device__ float g_bufB[(size_t)MAXN * kHC];
__device__ float g_bufC[(size_t)MAXN * kHC];
__device__ float g_attn[6 * (size_t)MAXN * kH];
__device__ int   g_rowptr[MAXN + 1];
__device__ int   g_deg[MAXN];
__device__ int   g_adj[MAXET];
__device__ int   g_bsum[256];

// ---------------- helpers ----------------
__device__ __forceinline__ uint32_t pack_half2(float x, float y) {
    __half2 h = __float22half2_rn(make_float2(x, y));
    return *(uint32_t*)&h;
}

// fp16 MMA m16n8k16, fp32 accumulate. A row-major, B col-major.
__device__ __forceinline__ void mma_f16_16x8x16(float* c, const uint32_t* a, const uint32_t* b) {
    asm volatile(
        "mma.sync.aligned.m16n8k16.row.col.f32.f16.f16.f32 "
        "{%0,%1,%2,%3}, {%4,%5,%6,%7}, {%8,%9}, {%0,%1,%2,%3};"
        : "+f"(c[0]), "+f"(c[1]), "+f"(c[2]), "+f"(c[3])
        : "r"(a[0]), "r"(a[1]), "r"(a[2]), "r"(a[3]), "r"(b[0]), "r"(b[1]));
}

// ---------------- fp16 mma.sync GEMM with fused attn epilogue ----------------
// C[M,Nc] = A[M,K] @ W[K,Nc]; 128 x BN tile, BK=32 halves, 8 warps 2(m)x4(n).
// SMEM A: word array [m][k2], stride 20 words (16 data + 4 pad). word = halves (2k2, 2k2+1).
// SMEM B: word array [k2][n], stride BN+4 words. word = halves (k=2k2, 2k2+1) of column n.
template <int BN, int AH, bool HIN, bool HOUT>
__global__ __launch_bounds__(256)
void tgemm_kernel(const void* __restrict__ Ain, const float* __restrict__ W,
                  void* __restrict__ Cout, int M, int K, int Nc,
                  const float* __restrict__ bias, int do_relu,
                  const float* __restrict__ avs, const float* __restrict__ avd,
                  float* __restrict__ as_n, float* __restrict__ ad_n)
{
    static constexpr int SAW = 20;          // A row stride in words
    static constexpr int SBW = BN + 4;      // B row stride in words
    static constexpr int NT  = BN / 32;
    static constexpr int NB2 = BN / 16;     // W loader iters (16*BN words / 256 thr)
    static constexpr int LOG2BN = (BN == 128) ? 7 : 6;

    __shared__ uint32_t sA[128 * SAW];
    __shared__ uint32_t sB[16 * SBW];

    const int tid = threadIdx.x;
    const int wid = tid >> 5;
    const int lid = tid & 31;
    const int g   = lid >> 2;
    const int tig = lid & 3;
    const int warp_m = wid & 1;
    const int warp_n = wid >> 1;

    const int rowBase = blockIdx.y * 128;
    const int colBase = blockIdx.x * BN;

    float acc[4][NT][4];
#pragma unroll
    for (int mt = 0; mt < 4; mt++)
#pragma unroll
        for (int nt = 0; nt < NT; nt++)
#pragma unroll
            for (int i = 0; i < 4; i++) acc[mt][nt][i] = 0.f;

    float4 aRegF[4];
    uint4  aRegH[2];
    float2 wReg[NB2];

    auto loadA = [&](int k0) {
        if (HIN) {
            const __half* A = (const __half*)Ain;
#pragma unroll
            for (int i = 0; i < 2; i++) {
                int idx = tid + 256 * i;
                int m = idx >> 2, c8 = idx & 3;
                int gr = rowBase + m;
                aRegH[i] = (gr < M) ? *(const uint4*)(A + (size_t)gr * K + k0 + c8 * 8)
                                    : make_uint4(0u, 0u, 0u, 0u);
            }
        } else {
            const float* A = (const float*)Ain;
#pragma unroll
            for (int i = 0; i < 4; i++) {
                int idx = tid + 256 * i;
                int m = idx >> 3, c4 = idx & 7;
                int gr = rowBase + m;
                aRegF[i] = (gr < M) ? *(const float4*)(A + (size_t)gr * K + k0 + c4 * 4)
                                    : make_float4(0.f, 0.f, 0.f, 0.f);
            }
        }
    };
    auto loadW = [&](int k0) {
#pragma unroll
        for (int i = 0; i < NB2; i++) {
            int idx = tid + 256 * i;
            int n  = idx & (BN - 1);
            int k2 = idx >> LOG2BN;
            wReg[i].x = W[(size_t)(k0 + 2 * k2)     * Nc + colBase + n];
            wReg[i].y = W[(size_t)(k0 + 2 * k2 + 1) * Nc + colBase + n];
        }
    };
    auto stsTiles = [&]() {
        if (HIN) {
#pragma unroll
            for (int i = 0; i < 2; i++) {
                int idx = tid + 256 * i;
                int m = idx >> 2, c8 = idx & 3;
                *(uint4*)(sA + m * SAW + c8 * 4) = aRegH[i];   // already half-pairs in k order
            }
        } else {
#pragma unroll
            for (int i = 0; i < 4; i++) {
                int idx = tid + 256 * i;
                int m = idx >> 3, c4 = idx & 7;
                float4 v = aRegF[i];
                uint2 w;
                w.x = pack_half2(v.x, v.y);
                w.y = pack_half2(v.z, v.w);
                *(uint2*)(sA + m * SAW + c4 * 2) = w;
            }
        }
#pragma unroll
        for (int i = 0; i < NB2; i++) {
            int idx = tid + 256 * i;
            int n  = idx & (BN - 1);
            int k2 = idx >> LOG2BN;
            sB[k2 * SBW + n] = pack_half2(wReg[i].x, wReg[i].y);
        }
    };

    const int nchunk = K / 32;
    loadA(0);
    loadW(0);

    for (int ch = 0; ch < nchunk; ch++) {
        stsTiles();
        __syncthreads();
        if (ch + 1 < nchunk) { loadA((ch + 1) * 32); loadW((ch + 1) * 32); }

#pragma unroll
        for (int kk = 0; kk < 2; kk++) {
            const int kb2 = kk * 8;
            uint32_t afr[4][4];
#pragma unroll
            for (int mt = 0; mt < 4; mt++) {
                int m = warp_m * 64 + mt * 16 + g;
                afr[mt][0] = sA[(m)     * SAW + kb2 + tig];
                afr[mt][1] = sA[(m + 8) * SAW + kb2 + tig];
                afr[mt][2] = sA[(m)     * SAW + kb2 + tig + 4];
                afr[mt][3] = sA[(m + 8) * SAW + kb2 + tig + 4];
            }
            uint32_t bfr[NT][2];
#pragma unroll
            for (int nt = 0; nt < NT; nt++) {
                int n = warp_n * (BN / 4) + nt * 8 + g;
                bfr[nt][0] = sB[(kb2 + tig)     * SBW + n];
                bfr[nt][1] = sB[(kb2 + tig + 4) * SBW + n];
            }
#pragma unroll
            for (int mt = 0; mt < 4; mt++)
#pragma unroll
                for (int nt = 0; nt < NT; nt++)
                    mma_f16_16x8x16(acc[mt][nt], afr[mt], bfr[nt]);
        }
        __syncthreads();
    }

    // ---- fused attn partials ----
    if (AH > 0) {
        const int h = (AH == 1) ? 0 : ((colBase + warp_n * (BN / 4)) >> 6);
#pragma unroll
        for (int mt = 0; mt < 4; mt++) {
            float s0 = 0.f, s1 = 0.f, d0 = 0.f, d1 = 0.f;
#pragma unroll
            for (int nt = 0; nt < NT; nt++) {
                int col = colBase + warp_n * (BN / 4) + nt * 8 + tig * 2;
                float a0 = avs[col], a1 = avs[col + 1];
                float b0 = avd[col], b1 = avd[col + 1];
                s0 += acc[mt][nt][0] * a0 + acc[mt][nt][1] * a1;
                s1 += acc[mt][nt][2] * a0 + acc[mt][nt][3] * a1;
                d0 += acc[mt][nt][0] * b0 + acc[mt][nt][1] * b1;
                d1 += acc[mt][nt][2] * b0 + acc[mt][nt][3] * b1;
            }
#pragma unroll
            for (int off = 1; off <= 2; off <<= 1) {
                s0 += __shfl_xor_sync(0xFFFFFFFFu, s0, off);
                s1 += __shfl_xor_sync(0xFFFFFFFFu, s1, off);
                d0 += __shfl_xor_sync(0xFFFFFFFFu, d0, off);
                d1 += __shfl_xor_sync(0xFFFFFFFFu, d1, off);
            }
            if (tig == 0) {
                int row0 = rowBase + warp_m * 64 + mt * 16 + g;
                int row1 = row0 + 8;
                if (row0 < M) {
                    atomicAdd(&as_n[(size_t)row0 * AH + h], s0);
                    atomicAdd(&ad_n[(size_t)row0 * AH + h], d0);
                }
                if (row1 < M) {
                    atomicAdd(&as_n[(size_t)row1 * AH + h], s1);
                    atomicAdd(&ad_n[(size_t)row1 * AH + h], d1);
                }
            }
        }
    }

    // ---- store C ----
#pragma unroll
    for (int mt = 0; mt < 4; mt++) {
        int row0 = rowBase + warp_m * 64 + mt * 16 + g;
        int row1 = row0 + 8;
#pragma unroll
        for (int nt = 0; nt < NT; nt++) {
            int col = colBase + warp_n * (BN / 4) + nt * 8 + tig * 2;
            float bx = 0.f, by = 0.f;
            if (bias) { bx = bias[col]; by = bias[col + 1]; }
            float2 v0 = make_float2(acc[mt][nt][0] + bx, acc[mt][nt][1] + by);
            float2 v1 = make_float2(acc[mt][nt][2] + bx, acc[mt][nt][3] + by);
            if (do_relu) {
                v0.x = fmaxf(v0.x, 0.f); v0.y = fmaxf(v0.y, 0.f);
                v1.x = fmaxf(v1.x, 0.f); v1.y = fmaxf(v1.y, 0.f);
            }
            if (HOUT) {
                __half2* Ch = (__half2*)Cout;
                if (row0 < M) Ch[((size_t)row0 * Nc + col) >> 1] = __float22half2_rn(v0);
                if (row1 < M) Ch[((size_t)row1 * Nc + col) >> 1] = __float22half2_rn(v1);
            } else {
                float* Cf = (float*)Cout;
                if (row0 < M) *(float2*)(Cf + (size_t)row0 * Nc + col) = v0;
                if (row1 < M) *(float2*)(Cf + (size_t)row1 * Nc + col) = v1;
            }
        }
    }
}

// ---------------- CSR build ----------------
__global__ void count_kernel(const int* __restrict__ ei, int E, int N, int* __restrict__ deg)
{
    int e = blockIdx.x * blockDim.x + threadIdx.x;
    int ET = E + N;
    if (e >= ET) return;
    int d = (e < E) ? ei[E + e] : (e - E);
    atomicAdd(&deg[d], 1);
}

__global__ void scan1_kernel(const int* __restrict__ deg, int* __restrict__ rowptr,
                             int* __restrict__ bsum, int N)
{
    __shared__ int sh[1024];
    int i = blockIdx.x * 1024 + threadIdx.x;
    int v = (i < N) ? deg[i] : 0;
    sh[threadIdx.x] = v;
    __syncthreads();
#pragma unroll
    for (int off = 1; off < 1024; off <<= 1) {
        int t = (threadIdx.x >= off) ? sh[threadIdx.x - off] : 0;
        __syncthreads();
        sh[threadIdx.x] += t;
        __syncthreads();
    }
    if (i < N) rowptr[i + 1] = sh[threadIdx.x];
    if (threadIdx.x == 1023) bsum[blockIdx.x] = sh[1023];
}

__global__ void scan2_kernel(int* __restrict__ bsum, int nb)
{
    if (threadIdx.x == 0) {
        int acc = 0;
        for (int i = 0; i < nb; i++) { int t = bsum[i]; bsum[i] = acc; acc += t; }
    }
}

__global__ void scan3_kernel(int* __restrict__ rowptr, const int* __restrict__ bsum, int N)
{
    int i = blockIdx.x * 1024 + threadIdx.x;
    if (i < N) rowptr[i + 1] += bsum[blockIdx.x];
    if (i == 0) rowptr[0] = 0;
}

__global__ void fill_kernel(const int* __restrict__ ei, int E, int N,
                            const int* __restrict__ rowptr, int* __restrict__ cur,
                            int* __restrict__ adj)
{
    int e = blockIdx.x * blockDim.x + threadIdx.x;
    int ET = E + N;
    if (e >= ET) return;
    int s, d;
    if (e < E) { s = ei[e]; d = ei[E + e]; } else { s = d = e - E; }
    int pos = rowptr[d] + atomicAdd(&cur[d], 1);
    adj[pos] = s;
}

// ---------------- fused gather (4-way unroll, half in/out) ----------------
__device__ __forceinline__ void acc8_half(float* acc, float a, uint4 r)
{
    const __half2* hp = (const __half2*)&r;
#pragma unroll
    for (int i = 0; i < 4; i++) {
        float2 f = __half22float2(hp[i]);
        acc[2 * i]     += a * f.x;
        acc[2 * i + 1] += a * f.y;
    }
}

__device__ __forceinline__ float edge_alpha(float as_v, float ad)
{
    float l = as_v + ad;
    l = (l > 0.f) ? l : 0.2f * l;
    return __expf(l);
}

__global__ __launch_bounds__(256) void gat_gather4_kernel(
    const int* __restrict__ rowptr, const int* __restrict__ adj,
    const __half* __restrict__ xl,
    const float* __restrict__ as_n, const float* __restrict__ ad_n,
    const float* __restrict__ bias, __half* __restrict__ out, int N)
{
    int w = (blockIdx.x * blockDim.x + threadIdx.x) >> 5;
    int lane = threadIdx.x & 31;
    if (w >= N) return;

    const int h   = lane >> 3;
    const int col = lane * 8;
    const float ad = ad_n[(size_t)w * 4 + h];

    float acc[8];
#pragma unroll
    for (int i = 0; i < 8; i++) acc[i] = 0.f;
    float den = 0.f;

    const int beg = rowptr[w], end = rowptr[w + 1];
    int j = beg;
    for (; j + 3 < end; j += 4) {
        int s0 = adj[j], s1 = adj[j + 1], s2 = adj[j + 2], s3 = adj[j + 3];
        float a0 = edge_alpha(as_n[(size_t)s0 * 4 + h], ad);
        float a1 = edge_alpha(as_n[(size_t)s1 * 4 + h], ad);
        float a2 = edge_alpha(as_n[(size_t)s2 * 4 + h], ad);
        float a3 = edge_alpha(as_n[(size_t)s3 * 4 + h], ad);
        uint4 r0 = *(const uint4*)(xl + (size_t)s0 * 256 + col);
        uint4 r1 = *(const uint4*)(xl + (size_t)s1 * 256 + col);
        uint4 r2 = *(const uint4*)(xl + (size_t)s2 * 256 + col);
        uint4 r3 = *(const uint4*)(xl + (size_t)s3 * 256 + col);
        den += (a0 + a1) + (a2 + a3);
        acc8_half(acc, a0, r0);
        acc8_half(acc, a1, r1);
        acc8_half(acc, a2, r2);
        acc8_half(acc, a3, r3);
    }
    for (; j < end; j++) {
        int s = adj[j];
        float a = edge_alpha(as_n[(size_t)s * 4 + h], ad);
        uint4 r = *(const uint4*)(xl + (size_t)s * 256 + col);
        den += a;
        acc8_half(acc, a, r);
    }

    float inv = 1.f / (den + 1e-16f);
    __half2 o[4];
#pragma unroll
    for (int i = 0; i < 4; i++) {
        float2 f;
        f.x = fmaxf(acc[2 * i]     * inv + bias[col + 2 * i],     0.f);
        f.y = fmaxf(acc[2 * i + 1] * inv + bias[col + 2 * i + 1], 0.f);
        o[i] = __float22half2_rn(f);
    }
    *(uint4*)(out + (size_t)w * 256 + col) = *(const uint4*)o;
}

__global__ __launch_bounds__(256) void gat_gather1_kernel(
    const int* __restrict__ rowptr, const int* __restrict__ adj,
    const __half* __restrict__ xl,
    const float* __restrict__ as_n, const float* __restrict__ ad_n,
    const float* __restrict__ bias, __half* __restrict__ out, int N)
{
    int w = (blockIdx.x * blockDim.x + threadIdx.x) >> 5;
    int lane = threadIdx.x & 31;
    if (w >= N) return;

    const int col = lane * 2;
    const float ad = ad_n[w];

    float acc0 = 0.f, acc1 = 0.f, den = 0.f;

    const int beg = rowptr[w], end = rowptr[w + 1];
    int j = beg;
    for (; j + 3 < end; j += 4) {
        int s0 = adj[j], s1 = adj[j + 1], s2 = adj[j + 2], s3 = adj[j + 3];
        float a0 = edge_alpha(as_n[s0], ad);
        float a1 = edge_alpha(as_n[s1], ad);
        float a2 = edge_alpha(as_n[s2], ad);
        float a3 = edge_alpha(as_n[s3], ad);
        float2 f0 = __half22float2(*(const __half2*)(xl + (size_t)s0 * 64 + col));
        float2 f1 = __half22float2(*(const __half2*)(xl + (size_t)s1 * 64 + col));
        float2 f2 = __half22float2(*(const __half2*)(xl + (size_t)s2 * 64 + col));
        float2 f3 = __half22float2(*(const __half2*)(xl + (size_t)s3 * 64 + col));
        den += (a0 + a1) + (a2 + a3);
        acc0 += a0 * f0.x + a1 * f1.x + a2 * f2.x + a3 * f3.x;
        acc1 += a0 * f0.y + a1 * f1.y + a2 * f2.y + a3 * f3.y;
    }
    for (; j < end; j++) {
        int s = adj[j];
        float a = edge_alpha(as_n[s], ad);
        float2 f = __half22float2(*(const __half2*)(xl + (size_t)s * 64 + col));
        den += a;
        acc0 += a * f.x;
        acc1 += a * f.y;
    }

    float inv = 1.f / (den + 1e-16f);
    float2 f;
    f.x = fmaxf(acc0 * inv + bias[col + 0], 0.f);
    f.y = fmaxf(acc1 * inv + bias[col + 1], 0.f);
    *(__half2*)(out + (size_t)w * 64 + col) = __float22half2_rn(f);
}

// ---------------- host orchestration ----------------
extern "C" void kernel_launch(void* const* d_in, const int* in_sizes, int n_in,
                              void* d_out, int out_size)
{
    const float* x   = (const float*)d_in[0];
    const int*   ei  = (const int*)d_in[1];
    const float* W1  = (const float*)d_in[2];
    const float* as1 = (const float*)d_in[3];
    const float* ad1 = (const float*)d_in[4];
    const float* b1  = (const float*)d_in[5];
    const float* W2  = (const float*)d_in[6];
    const float* as2 = (const float*)d_in[7];
    const float* ad2 = (const float*)d_in[8];
    const float* b2  = (const float*)d_in[9];
    const float* W3  = (const float*)d_in[10];
    const float* as3 = (const float*)d_in[11];
    const float* ad3 = (const float*)d_in[12];
    const float* b3  = (const float*)d_in[13];
    const float* Wfc = (const float*)d_in[14];
    const float* bfc = (const float*)d_in[15];
    float* out = (float*)d_out;

    int N  = in_sizes[0] / kIN;
    int E  = in_sizes[1] / 2;
    int ET = E + N;

    float *bufA, *bufB, *bufC, *attn;
    int *rowptr, *deg, *adj, *bsum;
    cudaGetSymbolAddress((void**)&bufA, g_bufA);
    cudaGetSymbolAddress((void**)&bufB, g_bufB);
    cudaGetSymbolAddress((void**)&bufC, g_bufC);
    cudaGetSymbolAddress((void**)&attn, g_attn);
    cudaGetSymbolAddress((void**)&rowptr, g_rowptr);
    cudaGetSymbolAddress((void**)&deg,    g_deg);
    cudaGetSymbolAddress((void**)&adj,    g_adj);
    cudaGetSymbolAddress((void**)&bsum,   g_bsum);

    size_t NH = (size_t)N * kH;
    float* pas1 = attn;
    float* pad1 = attn + NH;
    float* pas2 = attn + 2 * NH;
    float* pad2 = attn + 3 * NH;
    float* pas3 = attn + 4 * NH;
    float* pad3 = attn + 5 * NH;

    __half* bufAh = (__half*)bufA;
    __half* bufBh = (__half*)bufB;
    __half* bufCh = (__half*)bufC;

    int edgeBlocks = (ET + 255) / 256;
    int nodeWarpBlocks = (N + 7) / 8;
    int scanBlocks = (N + 1023) / 1024;

    dim3 grid256((kHC + 127) / 128, (N + 127) / 128);
    dim3 grid64(1, (N + 127) / 128);
    dim3 gridFC(kOUT / 128, (N + 127) / 128);

    // side stream + events for CSR || GEMM1 overlap (created once; no device memory)
    static cudaStream_t s2 = nullptr;
    static cudaEvent_t evFork = nullptr, evJoin = nullptr;
    if (!s2) {
        cudaStreamCreateWithFlags(&s2, cudaStreamNonBlocking);
        cudaEventCreateWithFlags(&evFork, cudaEventDisableTiming);
        cudaEventCreateWithFlags(&evJoin, cudaEventDisableTiming);
    }

    // attn zeroing must precede layer-1 GEMM epilogue atomics (main stream)
    cudaMemsetAsync(attn, 0, 6 * NH * sizeof(float));

    // fork: CSR build on s2, concurrent with layer-1 GEMM on main stream
    cudaEventRecord(evFork, 0);
    cudaStreamWaitEvent(s2, evFork, 0);

    cudaMemsetAsync(deg, 0, (size_t)N * sizeof(int), s2);
    count_kernel<<<edgeBlocks, 256, 0, s2>>>(ei, E, N, deg);
    scan1_kernel<<<scanBlocks, 1024, 0, s2>>>(deg, rowptr, bsum, N);
    scan2_kernel<<<1, 32, 0, s2>>>(bsum, scanBlocks);
    scan3_kernel<<<scanBlocks, 1024, 0, s2>>>(rowptr, bsum, N);
    cudaMemsetAsync(deg, 0, (size_t)N * sizeof(int), s2);
    fill_kernel<<<edgeBlocks, 256, 0, s2>>>(ei, E, N, rowptr, deg, adj);
    cudaEventRecord(evJoin, s2);

    // ---- layer 1 GEMM (independent of CSR) ----
    tgemm_kernel<128, 4, false, true><<<grid256, 256>>>(
        x, W1, bufA, N, kIN, kHC, nullptr, 0, as1, ad1, pas1, pad1);

    // join before first gather (needs CSR)
    cudaStreamWaitEvent(0, evJoin, 0);

    gat_gather4_kernel<<<nodeWarpBlocks, 256>>>(rowptr, adj, bufAh, pas1, pad1, b1, bufBh, N);

    // ---- layer 2 ----
    tgemm_kernel<128, 4, true, true><<<grid256, 256>>>(
        bufBh, W2, bufA, N, kHC, kHC, nullptr, 0, as2, ad2, pas2, pad2);
    gat_gather4_kernel<<<nodeWarpBlocks, 256>>>(rowptr, adj, bufAh, pas2, pad2, b2, bufCh, N);

    // ---- layer 3 ----
    tgemm_kernel<64, 1, true, true><<<grid64, 256>>>(
        bufCh, W3, bufA, N, kHC, kC, nullptr, 0, as3, ad3, pas3, pad3);
    gat_gather1_kernel<<<nodeWarpBlocks, 256>>>(rowptr, adj, bufAh, pas3, pad3, b3, bufBh, N);

    // ---- final fc ----
    tgemm_kernel<128, 0, true, false><<<gridFC, 256>>>(
        bufBh, Wfc, out, N, kC, kOUT, bfc, 1, nullptr, nullptr, nullptr, nullptr);
}